// round 7
// baseline (speedup 1.0000x reference)
#include <cuda_runtime.h>

#define TOTAL_QUBITS 24
#define DIM (1u << TOTAL_QUBITS)
#define BATCH 4

// 2-qubit gate on batched 2^24 statevector. Memory-bound streaming (256MB
// read + 256MB write, zero reuse). This variant: 8 consecutive rest indices
// per thread = two adjacent float4s per stream (group B = base+4), giving
// 8 in-flight LDG.128 and 1KB-contiguous warp segments per stream, with a
// single base computation (low register cost, unlike the failed R2 shape).
__global__ __launch_bounds__(256)
void quantum_gate_kernel(const float* __restrict__ state,
                         const float* __restrict__ matrix,
                         const int* __restrict__ q0p,
                         const int* __restrict__ q1p,
                         float* __restrict__ out)
{
    const int q0 = q0p[0];
    const int q1 = q1p[0];
    const int bq0 = TOTAL_QUBITS - 1 - q0;   // linear-index bit = HIGH bit of g
    const int bq1 = TOTAL_QUBITS - 1 - q1;   // linear-index bit = LOW  bit of g
    const int blo = bq0 < bq1 ? bq0 : bq1;
    const int bhi = bq0 < bq1 ? bq1 : bq0;

    float m[16];
#pragma unroll
    for (int i = 0; i < 16; i++) m[i] = __ldg(matrix + i);

    const unsigned off1 = 1u << bq1;                       // toggles low bit of g
    const unsigned off2 = 1u << bq0;                       // toggles high bit of g

    if (blo >= 3) {
        // ---- vectorized path: 8 consecutive rest indices / thread ----
        const unsigned oct_per_batch = DIM >> 5;           // 2^19 8-groups per batch
        unsigned t  = blockIdx.x * blockDim.x + threadIdx.x;
        unsigned b  = t >> 19;
        unsigned rv = t & (oct_per_batch - 1);
        if (b >= BATCH) return;

        const size_t boff = (size_t)b << TOTAL_QUBITS;
        unsigned r    = rv << 3;                           // rest index, multiple of 8
        unsigned low  = r & ((1u << blo) - 1);
        unsigned mid  = (r >> blo) & ((1u << (bhi - 1 - blo)) - 1);
        unsigned high = r >> (bhi - 1);
        unsigned base = low | (mid << (blo + 1)) | (high << (bhi + 1));

        const float* sp = state + boff;
        float*       op = out   + boff;

        // Front-batch all 8 loads (two adjacent float4s per stream).
        float4 a0 = __ldcs(reinterpret_cast<const float4*>(sp + base));
        float4 a1 = __ldcs(reinterpret_cast<const float4*>(sp + base + off1));
        float4 a2 = __ldcs(reinterpret_cast<const float4*>(sp + base + off2));
        float4 a3 = __ldcs(reinterpret_cast<const float4*>(sp + base + off1 + off2));
        float4 b0 = __ldcs(reinterpret_cast<const float4*>(sp + base + 4));
        float4 b1 = __ldcs(reinterpret_cast<const float4*>(sp + base + off1 + 4));
        float4 b2 = __ldcs(reinterpret_cast<const float4*>(sp + base + off2 + 4));
        float4 b3 = __ldcs(reinterpret_cast<const float4*>(sp + base + off1 + off2 + 4));

        float4 o0, o1, o2, o3;
#define APPLY(s0,s1,s2,s3,comp)                                                   \
        o0.comp = m[0]*s0.comp + m[1]*s1.comp + m[2]*s2.comp + m[3]*s3.comp;      \
        o1.comp = m[4]*s0.comp + m[5]*s1.comp + m[6]*s2.comp + m[7]*s3.comp;      \
        o2.comp = m[8]*s0.comp + m[9]*s1.comp + m[10]*s2.comp + m[11]*s3.comp;    \
        o3.comp = m[12]*s0.comp + m[13]*s1.comp + m[14]*s2.comp + m[15]*s3.comp;

        // Group A
        APPLY(a0,a1,a2,a3,x) APPLY(a0,a1,a2,a3,y) APPLY(a0,a1,a2,a3,z) APPLY(a0,a1,a2,a3,w)
        __stcs(reinterpret_cast<float4*>(op + base),               o0);
        __stcs(reinterpret_cast<float4*>(op + base + off1),        o1);
        __stcs(reinterpret_cast<float4*>(op + base + off2),        o2);
        __stcs(reinterpret_cast<float4*>(op + base + off1 + off2), o3);

        // Group B (adjacent float4)
        APPLY(b0,b1,b2,b3,x) APPLY(b0,b1,b2,b3,y) APPLY(b0,b1,b2,b3,z) APPLY(b0,b1,b2,b3,w)
        __stcs(reinterpret_cast<float4*>(op + base + 4),               o0);
        __stcs(reinterpret_cast<float4*>(op + base + off1 + 4),        o1);
        __stcs(reinterpret_cast<float4*>(op + base + off2 + 4),        o2);
        __stcs(reinterpret_cast<float4*>(op + base + off1 + off2 + 4), o3);
#undef APPLY
    } else {
        // ---- scalar fallback (gate bit in low 3 index bits) ----
        const unsigned oct_per_batch = DIM >> 5;
        unsigned t  = blockIdx.x * blockDim.x + threadIdx.x;
        unsigned b  = t >> 19;
        unsigned rv = t & (oct_per_batch - 1);
        if (b >= BATCH) return;

        const size_t boff = (size_t)b << TOTAL_QUBITS;
        const float* sp = state + boff;
        float*       op = out   + boff;
#pragma unroll
        for (int i = 0; i < 8; i++) {
            unsigned r    = (rv << 3) + i;
            unsigned low  = r & ((1u << blo) - 1);
            unsigned midmask = (bhi - 1 - blo) >= 32 ? 0xFFFFFFFFu
                                                     : ((1u << (bhi - 1 - blo)) - 1);
            unsigned mid  = (r >> blo) & midmask;
            unsigned high = r >> (bhi - 1);
            unsigned base = low | (mid << (blo + 1)) | (high << (bhi + 1));

            float s0 = sp[base];
            float s1 = sp[base + off1];
            float s2 = sp[base + off2];
            float s3 = sp[base + off1 + off2];

            op[base]               = m[0]*s0  + m[1]*s1  + m[2]*s2  + m[3]*s3;
            op[base + off1]        = m[4]*s0  + m[5]*s1  + m[6]*s2  + m[7]*s3;
            op[base + off2]        = m[8]*s0  + m[9]*s1  + m[10]*s2 + m[11]*s3;
            op[base + off1 + off2] = m[12]*s0 + m[13]*s1 + m[14]*s2 + m[15]*s3;
        }
    }
}

extern "C" void kernel_launch(void* const* d_in, const int* in_sizes, int n_in,
                              void* d_out, int out_size)
{
    const float* state  = (const float*)d_in[0];
    const float* matrix = (const float*)d_in[1];
    const int*   q0     = (const int*)d_in[2];
    const int*   q1     = (const int*)d_in[3];
    float*       out    = (float*)d_out;

    const unsigned total_threads = BATCH * (DIM >> 5);     // 2^21
    const unsigned block = 256;
    const unsigned grid  = (total_threads + block - 1) / block;   // 8192
    quantum_gate_kernel<<<grid, block>>>(state, matrix, q0, q1, out);
}

// round 8
// speedup vs baseline: 1.1405x; 1.1405x over previous
#include <cuda_runtime.h>

#define TOTAL_QUBITS 24
#define DIM (1u << TOTAL_QUBITS)
#define BATCH 4

// 2-qubit gate on batched 2^24 statevector. Pure streaming: 256MB read +
// 256MB write, zero reuse -> memory-bound at the mixed-stream HBM ceiling
// (~6.37 TB/s, 80% of spec; confirmed across 7 kernel variants).
// FINAL shape: one float4-group (4 consecutive rest indices) per thread,
// 32 regs / 83% occupancy, one-shot CTAs (CTA churn overlaps load ramp with
// store drain), warp-coalesced 128-bit LD/ST on all 8 streams, evict-first
// hints. Falsified alternatives: deeper MLP (reg cost), persistent grid
// (kills chip-level MLP), thread-adjacent vectors (breaks coalescing),
// L1 bypass / block-size changes (neutral).
__global__ __launch_bounds__(256)
void quantum_gate_kernel(const float* __restrict__ state,
                         const float* __restrict__ matrix,
                         const int* __restrict__ q0p,
                         const int* __restrict__ q1p,
                         float* __restrict__ out)
{
    const int q0 = q0p[0];
    const int q1 = q1p[0];
    const int bq0 = TOTAL_QUBITS - 1 - q0;   // linear-index bit = HIGH bit of g
    const int bq1 = TOTAL_QUBITS - 1 - q1;   // linear-index bit = LOW  bit of g
    const int blo = bq0 < bq1 ? bq0 : bq1;
    const int bhi = bq0 < bq1 ? bq1 : bq0;

    float m[16];
#pragma unroll
    for (int i = 0; i < 16; i++) m[i] = __ldg(matrix + i);

    const unsigned vec_per_batch = DIM >> 4;               // 2^20 groups per batch
    unsigned t = blockIdx.x * blockDim.x + threadIdx.x;
    unsigned b  = t >> 20;
    unsigned rv = t & (vec_per_batch - 1);
    if (b >= BATCH) return;

    const size_t boff = (size_t)b << TOTAL_QUBITS;
    const unsigned off1 = 1u << bq1;                       // toggles low bit of g
    const unsigned off2 = 1u << bq0;                       // toggles high bit of g

    if (blo >= 2) {
        // ---- vectorized path (actual case: gate bits 13 and 20) ----
        unsigned r    = rv << 2;
        unsigned low  = r & ((1u << blo) - 1);
        unsigned mid  = (r >> blo) & ((1u << (bhi - 1 - blo)) - 1);
        unsigned high = r >> (bhi - 1);
        unsigned base = low | (mid << (blo + 1)) | (high << (bhi + 1));

        const float* sp = state + boff;
        float*       op = out   + boff;

        float4 s0 = __ldcs(reinterpret_cast<const float4*>(sp + base));
        float4 s1 = __ldcs(reinterpret_cast<const float4*>(sp + base + off1));
        float4 s2 = __ldcs(reinterpret_cast<const float4*>(sp + base + off2));
        float4 s3 = __ldcs(reinterpret_cast<const float4*>(sp + base + off1 + off2));

        float4 o0, o1, o2, o3;
#define APPLY(comp)                                                              \
        o0.comp = m[0]*s0.comp + m[1]*s1.comp + m[2]*s2.comp + m[3]*s3.comp;     \
        o1.comp = m[4]*s0.comp + m[5]*s1.comp + m[6]*s2.comp + m[7]*s3.comp;     \
        o2.comp = m[8]*s0.comp + m[9]*s1.comp + m[10]*s2.comp + m[11]*s3.comp;   \
        o3.comp = m[12]*s0.comp + m[13]*s1.comp + m[14]*s2.comp + m[15]*s3.comp;
        APPLY(x) APPLY(y) APPLY(z) APPLY(w)
#undef APPLY

        __stcs(reinterpret_cast<float4*>(op + base),               o0);
        __stcs(reinterpret_cast<float4*>(op + base + off1),        o1);
        __stcs(reinterpret_cast<float4*>(op + base + off2),        o2);
        __stcs(reinterpret_cast<float4*>(op + base + off1 + off2), o3);
    } else {
        // ---- scalar fallback (gate bit in low 2 index bits) ----
        const float* sp = state + boff;
        float*       op = out   + boff;
#pragma unroll
        for (int i = 0; i < 4; i++) {
            unsigned r    = (rv << 2) + i;
            unsigned low  = r & ((1u << blo) - 1);
            unsigned midmask = (bhi - 1 - blo) >= 32 ? 0xFFFFFFFFu
                                                     : ((1u << (bhi - 1 - blo)) - 1);
            unsigned mid  = (r >> blo) & midmask;
            unsigned high = r >> (bhi - 1);
            unsigned base = low | (mid << (blo + 1)) | (high << (bhi + 1));

            float s0 = sp[base];
            float s1 = sp[base + off1];
            float s2 = sp[base + off2];
            float s3 = sp[base + off1 + off2];

            op[base]               = m[0]*s0  + m[1]*s1  + m[2]*s2  + m[3]*s3;
            op[base + off1]        = m[4]*s0  + m[5]*s1  + m[6]*s2  + m[7]*s3;
            op[base + off2]        = m[8]*s0  + m[9]*s1  + m[10]*s2 + m[11]*s3;
            op[base + off1 + off2] = m[12]*s0 + m[13]*s1 + m[14]*s2 + m[15]*s3;
        }
    }
}

extern "C" void kernel_launch(void* const* d_in, const int* in_sizes, int n_in,
                              void* d_out, int out_size)
{
    const float* state  = (const float*)d_in[0];
    const float* matrix = (const float*)d_in[1];
    const int*   q0     = (const int*)d_in[2];
    const int*   q1     = (const int*)d_in[3];
    float*       out    = (float*)d_out;

    const unsigned total_threads = BATCH * (DIM >> 4);     // 2^22
    const unsigned block = 256;
    const unsigned grid  = (total_threads + block - 1) / block;   // 16384
    quantum_gate_kernel<<<grid, block>>>(state, matrix, q0, q1, out);
}

// round 9
// speedup vs baseline: 1.1476x; 1.0062x over previous
#include <cuda_runtime.h>

#define TOTAL_QUBITS 24
#define DIM (1u << TOTAL_QUBITS)
#define BATCH 4

// 2-qubit gate on batched 2^24 statevector. Pure streaming: 256MB read +
// 256MB write, zero reuse -> memory-bound at the mixed-stream HBM ceiling
// (~6.37 TB/s, 80% of spec; confirmed across 8 kernel variants / rounds).
// ROOFLINE shape: one float4-group (4 consecutive rest indices) per thread,
// 32 regs / ~83% occupancy, one-shot CTAs (CTA churn overlaps load ramp with
// store drain), warp-coalesced 128-bit LD/ST on all 8 streams, evict-first
// hints. Falsified: deeper MLP (reg cost), persistent grid (kills chip-level
// MLP), thread-adjacent vectors (breaks coalescing). Neutral: L1 bypass,
// block-size changes.
__global__ __launch_bounds__(256)
void quantum_gate_kernel(const float* __restrict__ state,
                         const float* __restrict__ matrix,
                         const int* __restrict__ q0p,
                         const int* __restrict__ q1p,
                         float* __restrict__ out)
{
    const int q0 = q0p[0];
    const int q1 = q1p[0];
    const int bq0 = TOTAL_QUBITS - 1 - q0;   // linear-index bit = HIGH bit of g
    const int bq1 = TOTAL_QUBITS - 1 - q1;   // linear-index bit = LOW  bit of g
    const int blo = bq0 < bq1 ? bq0 : bq1;
    const int bhi = bq0 < bq1 ? bq1 : bq0;

    float m[16];
#pragma unroll
    for (int i = 0; i < 16; i++) m[i] = __ldg(matrix + i);

    const unsigned vec_per_batch = DIM >> 4;               // 2^20 groups per batch
    unsigned t = blockIdx.x * blockDim.x + threadIdx.x;
    unsigned b  = t >> 20;
    unsigned rv = t & (vec_per_batch - 1);
    if (b >= BATCH) return;

    const size_t boff = (size_t)b << TOTAL_QUBITS;
    const unsigned off1 = 1u << bq1;                       // toggles low bit of g
    const unsigned off2 = 1u << bq0;                       // toggles high bit of g

    if (blo >= 2) {
        // ---- vectorized path (actual case: gate bits 13 and 20) ----
        unsigned r    = rv << 2;
        unsigned low  = r & ((1u << blo) - 1);
        unsigned mid  = (r >> blo) & ((1u << (bhi - 1 - blo)) - 1);
        unsigned high = r >> (bhi - 1);
        unsigned base = low | (mid << (blo + 1)) | (high << (bhi + 1));

        const float* sp = state + boff;
        float*       op = out   + boff;

        float4 s0 = __ldcs(reinterpret_cast<const float4*>(sp + base));
        float4 s1 = __ldcs(reinterpret_cast<const float4*>(sp + base + off1));
        float4 s2 = __ldcs(reinterpret_cast<const float4*>(sp + base + off2));
        float4 s3 = __ldcs(reinterpret_cast<const float4*>(sp + base + off1 + off2));

        float4 o0, o1, o2, o3;
#define APPLY(comp)                                                              \
        o0.comp = m[0]*s0.comp + m[1]*s1.comp + m[2]*s2.comp + m[3]*s3.comp;     \
        o1.comp = m[4]*s0.comp + m[5]*s1.comp + m[6]*s2.comp + m[7]*s3.comp;     \
        o2.comp = m[8]*s0.comp + m[9]*s1.comp + m[10]*s2.comp + m[11]*s3.comp;   \
        o3.comp = m[12]*s0.comp + m[13]*s1.comp + m[14]*s2.comp + m[15]*s3.comp;
        APPLY(x) APPLY(y) APPLY(z) APPLY(w)
#undef APPLY

        __stcs(reinterpret_cast<float4*>(op + base),               o0);
        __stcs(reinterpret_cast<float4*>(op + base + off1),        o1);
        __stcs(reinterpret_cast<float4*>(op + base + off2),        o2);
        __stcs(reinterpret_cast<float4*>(op + base + off1 + off2), o3);
    } else {
        // ---- scalar fallback (gate bit in low 2 index bits) ----
        const float* sp = state + boff;
        float*       op = out   + boff;
#pragma unroll
        for (int i = 0; i < 4; i++) {
            unsigned r    = (rv << 2) + i;
            unsigned low  = r & ((1u << blo) - 1);
            unsigned midmask = (bhi - 1 - blo) >= 32 ? 0xFFFFFFFFu
                                                     : ((1u << (bhi - 1 - blo)) - 1);
            unsigned mid  = (r >> blo) & midmask;
            unsigned high = r >> (bhi - 1);
            unsigned base = low | (mid << (blo + 1)) | (high << (bhi + 1));

            float s0 = sp[base];
            float s1 = sp[base + off1];
            float s2 = sp[base + off2];
            float s3 = sp[base + off1 + off2];

            op[base]               = m[0]*s0  + m[1]*s1  + m[2]*s2  + m[3]*s3;
            op[base + off1]        = m[4]*s0  + m[5]*s1  + m[6]*s2  + m[7]*s3;
            op[base + off2]        = m[8]*s0  + m[9]*s1  + m[10]*s2 + m[11]*s3;
            op[base + off1 + off2] = m[12]*s0 + m[13]*s1 + m[14]*s2 + m[15]*s3;
        }
    }
}

extern "C" void kernel_launch(void* const* d_in, const int* in_sizes, int n_in,
                              void* d_out, int out_size)
{
    const float* state  = (const float*)d_in[0];
    const float* matrix = (const float*)d_in[1];
    const int*   q0     = (const int*)d_in[2];
    const int*   q1     = (const int*)d_in[3];
    float*       out    = (float*)d_out;

    const unsigned total_threads = BATCH * (DIM >> 4);     // 2^22
    const unsigned block = 256;
    const unsigned grid  = (total_threads + block - 1) / block;   // 16384
    quantum_gate_kernel<<<grid, block>>>(state, matrix, q0, q1, out);
}